// round 17
// baseline (speedup 1.0000x reference)
#include <cuda_runtime.h>
#include <math.h>

// Problem constants
#define BATCH 16
#define LROWS 192   // 6*L rows of raw
#define AC    2046  // attributor columns
#define MC    2048  // M = A + 2
#define LD    32    // L (W_2 output dim)
#define TM    128   // columns of m per block in main kernel
#define MB    (MC / TM)   // 16 m-blocks

// Scratch (device globals; no allocation allowed)
__device__ float g_wq[BATCH][2][64];   // wq[b][n][j]
__device__ float g_wk[BATCH][2][64];   // wk[b][n][j]

// ---------------------------------------------------------------------------
// Kernel 1 (prep): wq/wk folds + d_out zeroing ONLY (33 blocks x 128 thr).
// The adj/iw packing now lives in main's prologue (hidden under streaming).
// ---------------------------------------------------------------------------
__global__ __launch_bounds__(128) void prep_kernel(
    const float* __restrict__ user, const float* __restrict__ item,
    const float* __restrict__ W2, float* __restrict__ out) {

    int blk = blockIdx.x;
    int t = threadIdx.x;

    if (blk < 32) {
        int b = blk >> 1;
        int n = blk & 1;
        const float* src = (n ? item : user) + b * LROWS;
        __shared__ float W2s[128 * 33];   // padded rows: conflict-free both ways
        __shared__ float xr[128];
        __shared__ float qs[32];
        __shared__ float ks[32];

        xr[t] = fmaxf(src[t], 0.0f);
        #pragma unroll
        for (int i = 0; i < 32; i++) {
            int idx = t + i * 128;            // 0..4095
            W2s[(idx >> 5) * 33 + (idx & 31)] = W2[idx];
        }
        __syncthreads();

        if (t < 32) {
            float s = 0.0f;
            #pragma unroll
            for (int j = 0; j < 64; j++) s = fmaf(xr[j], W2s[j * 33 + t], s);
            qs[t] = s;
        } else if (t < 64) {
            int l = t - 32;
            float s = 0.0f;
            #pragma unroll
            for (int j = 0; j < 64; j++) s = fmaf(xr[64 + j], W2s[(64 + j) * 33 + l], s);
            ks[l] = s;
        }
        __syncthreads();
        if (t < 64) {
            float swq = 0.0f, swk = 0.0f;
            #pragma unroll
            for (int l = 0; l < 32; l++) {
                swq = fmaf(W2s[t * 33 + l],        ks[l], swq);
                swk = fmaf(W2s[(64 + t) * 33 + l], qs[l], swk);
            }
            g_wq[b][n][t] = swq;
            g_wk[b][n][t] = swk;
        }
    } else {
        // zero d_out (1024 floats) for main's atomics
        float4 z = make_float4(0.f, 0.f, 0.f, 0.f);
        ((float4*)out)[t]       = z;
        ((float4*)out)[t + 128] = z;
    }
}

// ---------------------------------------------------------------------------
// Kernel 2 (main): R6 streaming pass + fused projection epilogue, with the
// adj/iw packing folded into the prologue as pure overlapped loads.
// grid (mb=16, b=16), 384 threads.
//   t <  128: load wq/wk
//   t >= 128: stage W2e (2 x float4) + gather adj/iw for this block's slots
//             (consumed only at the causal phase -> latency fully hidden)
// ---------------------------------------------------------------------------
__global__ __launch_bounds__(384) void main_kernel(
    const float* __restrict__ user, const float* __restrict__ item,
    const float* __restrict__ attributor, const float* __restrict__ W1,
    const float* __restrict__ W2,
    const float* __restrict__ adj, const float* __restrict__ iw,
    float* __restrict__ out) {

    __shared__ float Vsh[64][TM + 1];
    __shared__ float hq_sh[2][TM];
    __shared__ float hk_sh[2][TM];
    __shared__ float c_sh[2][TM];
    __shared__ float wq_sh[2][64];
    __shared__ float wk_sh[2][64];
    __shared__ float W2e[64][LD];      // W2 rows 128..191 (value projection)
    __shared__ float Ssh[2 * 64];      // partial S for this block
    __shared__ float aA[2][TM], aP[2][TM], aR[2][TM];

    int b  = blockIdx.y;
    int mb = blockIdx.x;
    int t  = threadIdx.x;
    int group = t >> 7;          // 0,1,2
    int ml = t & (TM - 1);
    int m  = mb * TM + ml;

    if (t < 128) {
        ((float*)wq_sh)[t] = ((const float*)g_wq[b])[t];
        ((float*)wk_sh)[t] = ((const float*)g_wk[b])[t];
    } else {
        int r = t - 128;                       // 0..255
        ((float4*)W2e)[r]       = ((const float4*)(W2 + 128 * LD))[r];
        ((float4*)W2e)[r + 256] = ((const float4*)(W2 + 128 * LD))[r + 256];
        // adj/iw gather: 256 threads cover 128 slots x 2 n-values.
        // Consumed only at the causal phase (after streaming + syncthreads),
        // so these scattered loads hide under the streaming phase.
        int mm = r >> 1;                       // slot 0..127
        int n  = r & 1;
        int mg = mb * TM + mm;                 // node index
        int coln = n ? (MC - 1) : 0;
        float a = adj[(size_t)mg * MC + coln];
        aA[n][mm] = a;
        aP[n][mm] = a * iw[(size_t)mg * MC + coln];
        aR[n][mm] = adj[(size_t)coln * MC + mg] * iw[(size_t)coln * MC + mg];
    }
    __syncthreads();

    bool isU = (m == 0), isI = (m == MC - 1);
    bool special = isU || isI;
    int mm1 = special ? 0 : (m - 1);    // safe offset (never deref OOB)
    const float* ap = attributor + ((size_t)b * LROWS + group * 64) * AC + mm1;
    const float* wp = W1 + (size_t)(group * 64) * AC + mm1;

    if (group < 2) {
        const float (*wsel)[64] = (group == 0) ? wq_sh : wk_sh;
        float h0 = 0.0f, h1 = 0.0f;
        if (special) {
            const float* up = (isU ? user : item) + b * LROWS + group * 64;
            #pragma unroll
            for (int j = 0; j < 64; j++) {
                float x = fmaxf(up[j], 0.0f);
                h0 = fmaf(x, wsel[0][j], h0);
                h1 = fmaf(x, wsel[1][j], h1);
            }
        } else {
            #pragma unroll 2
            for (int jb = 0; jb < 64; jb += 8) {
                float av[8], wv[8];
                #pragma unroll
                for (int u = 0; u < 8; u++) av[u] = ap[(size_t)(jb + u) * AC];
                #pragma unroll
                for (int u = 0; u < 8; u++) wv[u] = wp[(size_t)(jb + u) * AC];
                #pragma unroll
                for (int u = 0; u < 8; u++) {
                    float x = fmaxf(av[u] * wv[u], 0.0f);
                    h0 = fmaf(x, wsel[0][jb + u], h0);
                    h1 = fmaf(x, wsel[1][jb + u], h1);
                }
            }
        }
        if (group == 0) { hq_sh[0][ml] = h0; hq_sh[1][ml] = h1; }
        else            { hk_sh[0][ml] = h0; hk_sh[1][ml] = h1; }
    } else {
        if (special) {
            const float* up = (isU ? user : item) + b * LROWS + 128;
            #pragma unroll
            for (int j = 0; j < 64; j++) Vsh[j][ml] = fmaxf(up[j], 0.0f);
        } else {
            #pragma unroll 2
            for (int jb = 0; jb < 64; jb += 8) {
                float av[8], wv[8];
                #pragma unroll
                for (int u = 0; u < 8; u++) av[u] = ap[(size_t)(jb + u) * AC];
                #pragma unroll
                for (int u = 0; u < 8; u++) wv[u] = wp[(size_t)(jb + u) * AC];
                #pragma unroll
                for (int u = 0; u < 8; u++)
                    Vsh[jb + u][ml] = fmaxf(av[u] * wv[u], 0.0f);
            }
        }
    }
    __syncthreads();

    // causal[b, m, col_n] = sigmoid(h[m,n] - h[n,m]) * adj[m, col_n]
    if (t < 256) {
        int n  = t >> 7;
        int mm = t & (TM - 1);
        float d = hq_sh[n][mm] * aP[n][mm] - hk_sh[n][mm] * aR[n][mm];
        c_sh[n][mm] = aA[n][mm] / (1.0f + expf(-d));
    }
    __syncthreads();

    // partial S[n][j] = sum_mm Vsh[j][mm] * c_sh[n][mm]
    if (t < 128) {
        int n = t >> 6;
        int j = t & 63;
        float s = 0.0f;
        #pragma unroll 8
        for (int mm = 0; mm < TM; mm++)
            s = fmaf(Vsh[j][mm], c_sh[n][mm], s);
        Ssh[t] = s;
    }
    __syncthreads();

    // fused projection: out[b,l,n] += sum_j W2e[j][l] * S[n][j]
    if (t < 64) {
        int l = t >> 1;
        int n = t & 1;
        float s = 0.0f;
        #pragma unroll
        for (int j = 0; j < 64; j++)
            s = fmaf(W2e[j][l], Ssh[n * 64 + j], s);
        atomicAdd(&out[b * 64 + l * 2 + n], s);
    }
}

extern "C" void kernel_launch(void* const* d_in, const int* in_sizes, int n_in,
                              void* d_out, int out_size) {
    const float* user       = (const float*)d_in[0];
    const float* item       = (const float*)d_in[1];
    const float* attributor = (const float*)d_in[2];
    const float* adj        = (const float*)d_in[3];
    const float* iw         = (const float*)d_in[4];
    const float* W1         = (const float*)d_in[5];
    const float* W2         = (const float*)d_in[6];
    float* out = (float*)d_out;

    prep_kernel<<<33, 128>>>(user, item, W2, out);
    main_kernel<<<dim3(MB, BATCH), 384>>>(user, item, attributor, W1, W2, adj, iw, out);
}